// round 7
// baseline (speedup 1.0000x reference)
#include <cuda_runtime.h>
#include <cuda_fp16.h>
#include <cuda_bf16.h>
#include <cstdint>
#include <cstddef>

// ---------------- problem constants ----------------
#define IN_F   1024
#define OUT_F  1024
#define MAX_TOKENS 32768
#define TILE_M 256
#define TILE_N 128

#define SM_STRIDE 2064    // 2048B row + 16B pad (conflict-free gathers)

// ---------------- scratch: bf16 fragment-major operand layouts ----------------
// g_xa: [mg = token/16][kb = 64 (k16 blocks)][lane = 32][16B = {a0,a1,a2,a3}]
__device__ __align__(16) __nv_bfloat16 g_xa[(size_t)MAX_TOKENS * IN_F];
__device__ float g_xs[MAX_TOKENS];
// g_wb: [ng = ocol/8][kbp = 32][lane = 32][16B = {b0 even kb, b1 even, b0 odd, b1 odd}]
__device__ __align__(16) __nv_bfloat16 g_wb[(size_t)OUT_F * IN_F];
__device__ float g_ws[OUT_F];

// ---------------- helpers ----------------
static __device__ __forceinline__ void mma_bf16(float* c, uint32_t a0, uint32_t a1,
                                                uint32_t a2, uint32_t a3,
                                                uint32_t b0, uint32_t b1) {
    asm volatile(
        "mma.sync.aligned.m16n8k16.row.col.f32.bf16.bf16.f32 "
        "{%0,%1,%2,%3}, {%4,%5,%6,%7}, {%8,%9}, {%0,%1,%2,%3};"
        : "+f"(c[0]), "+f"(c[1]), "+f"(c[2]), "+f"(c[3])
        : "r"(a0), "r"(a1), "r"(a2), "r"(a3), "r"(b0), "r"(b1));
}
static __device__ __forceinline__ uint32_t bf16x2(float lo, float hi) {
    return (uint32_t)__bfloat16_as_ushort(__float2bfloat16_rn(lo))
         | ((uint32_t)__bfloat16_as_ushort(__float2bfloat16_rn(hi)) << 16);
}

// ---------------- fused prep kernel ----------------
__global__ void __launch_bounds__(512) prep_kernel(const float* __restrict__ x,
                                                   const float* __restrict__ w,
                                                   int qBlocks) {
    __shared__ int8_t sm[16 * SM_STRIDE];
    int tid = threadIdx.x, warp = tid >> 5, lane = tid & 31;

    if ((int)blockIdx.x < qBlocks) {
        // ---- activation quantization: 16 tokens per block ----
        int mg = blockIdx.x;
        int t = mg * 16 + warp;
        const float4* xr = (const float4*)(x + (size_t)t * IN_F);
        float4 v[8];
        float m = 0.0f;
#pragma unroll
        for (int i = 0; i < 8; i++) {
            v[i] = xr[lane + 32 * i];
            m = fmaxf(m, fmaxf(fmaxf(fabsf(v[i].x), fabsf(v[i].y)),
                               fmaxf(fabsf(v[i].z), fabsf(v[i].w))));
        }
#pragma unroll
        for (int o = 16; o > 0; o >>= 1) m = fmaxf(m, __shfl_xor_sync(0xFFFFFFFFu, m, o));
        float scale = __fdiv_rn(fmaxf(m, 1e-8f), 127.0f);

#pragma unroll
        for (int i = 0; i < 8; i++) {
            float q0 = fminf(fmaxf(rintf(__fdiv_rn(v[i].x, scale)), -128.0f), 127.0f);
            float q1 = fminf(fmaxf(rintf(__fdiv_rn(v[i].y, scale)), -128.0f), 127.0f);
            float q2 = fminf(fmaxf(rintf(__fdiv_rn(v[i].z, scale)), -128.0f), 127.0f);
            float q3 = fminf(fmaxf(rintf(__fdiv_rn(v[i].w, scale)), -128.0f), 127.0f);
            uint2 pr = make_uint2(bf16x2(q0, q1), bf16x2(q2, q3));
            *(uint2*)(sm + warp * SM_STRIDE + 8 * lane + 256 * i) = pr;
        }
        if (lane == 0) g_xs[t] = scale;
        __syncthreads();

#pragma unroll
        for (int it = 0; it < 4; it++) {
            int u = tid + it * 512;
            int kb = u >> 5, l2 = u & 31;
            int g = l2 >> 2, t4 = l2 & 3;
            int bo = kb * 32 + t4 * 4;
            uint4 f;
            f.x = *(const uint32_t*)(sm + g * SM_STRIDE + bo);
            f.y = *(const uint32_t*)(sm + (g + 8) * SM_STRIDE + bo);
            f.z = *(const uint32_t*)(sm + g * SM_STRIDE + bo + 16);
            f.w = *(const uint32_t*)(sm + (g + 8) * SM_STRIDE + bo + 16);
            *(uint4*)((int8_t*)g_xa + ((((size_t)mg * 64 + kb) << 5) + l2) * 16) = f;
        }
    } else {
        // ---- weight binarize: 16 rows per block ----
        int wb = blockIdx.x - qBlocks;
        int o = wb * 16 + warp;
        const float4* wr = (const float4*)(w + (size_t)o * IN_F);
        float am[8];
#pragma unroll
        for (int i = 0; i < 8; i++) {
            float4 v = wr[lane + 32 * i];
            uint2 pr;
            pr.x = (((v.x > 0.0f) ? 0x3F80u : 0xBF80u))
                 | (((v.y > 0.0f) ? 0x3F80u : 0xBF80u) << 16);
            pr.y = (((v.z > 0.0f) ? 0x3F80u : 0xBF80u))
                 | (((v.w > 0.0f) ? 0x3F80u : 0xBF80u) << 16);
            *(uint2*)(sm + warp * SM_STRIDE + 8 * lane + 256 * i) = pr;
            am[i] = fmaxf(fmaxf(fabsf(v.x), fabsf(v.y)), fmaxf(fabsf(v.z), fabsf(v.w)));
        }
#pragma unroll
        for (int i = 0; i < 8; i++)
#pragma unroll
            for (int off = 16; off > 0; off >>= 1)
                am[i] = fmaxf(am[i], __shfl_xor_sync(0xFFFFFFFFu, am[i], off));
        if (lane == 0) {
            float s = 0.0f;
#pragma unroll
            for (int i = 0; i < 8; i++)
                s += __half2float(__float2half_rn(fmaxf(am[i], 1e-8f)));
            g_ws[o] = s * 0.125f;
        }
        __syncthreads();

#pragma unroll
        for (int it = 0; it < 4; it++) {
            int u = tid + it * 512;
            int nh = u >> 10, kbp = (u >> 5) & 31, l2 = u & 31;
            int c = l2 >> 2, t4 = l2 & 3;
            int row = nh * 8 + c;
            int bo = kbp * 64 + t4 * 4;
            uint4 f;
            f.x = *(const uint32_t*)(sm + row * SM_STRIDE + bo);
            f.y = *(const uint32_t*)(sm + row * SM_STRIDE + bo + 16);
            f.z = *(const uint32_t*)(sm + row * SM_STRIDE + bo + 32);
            f.w = *(const uint32_t*)(sm + row * SM_STRIDE + bo + 48);
            int ng = wb * 2 + nh;
            *(uint4*)((int8_t*)g_wb + ((((size_t)ng * 32 + kbp) << 5) + l2) * 16) = f;
        }
    }
}

// ---------------- GEMM: LDG.128 + bf16 MMA, software-pipelined B prefetch ----------------
__global__ void __launch_bounds__(512, 1)
onebit_gemm_kernel(const float* __restrict__ bias, float* __restrict__ out) {
    int tid = threadIdx.x, warp = tid >> 5, lane = tid & 31;
    int wm = warp >> 2;            // 0..3 -> 64-row slab of 256
    int wn = warp & 3;             // 0..3 -> 32-col slab of 128
    int n_blk = blockIdx.x & 7;
    int m_blk = blockIdx.x >> 3;
    int m0 = m_blk * TILE_M, n0 = n_blk * TILE_N;

    int mgB = m_blk * 16 + wm * 4;
    int ngB = n_blk * 16 + wn * 4;

    // per-warp base pointers (uint4 units)
    const uint4* Abase = (const uint4*)g_xa + (((size_t)mgB * 64) << 5) + lane;
    const uint4* Bbase = (const uint4*)g_wb + (((size_t)ngB * 32) << 5) + lane;
    // A: fragment (i, kb) at Abase + ((i*64 + kb) << 5)
    // B: fragment (j, kbp) at Bbase + ((j*32 + kbp) << 5)

    float acc[4][4][4];
#pragma unroll
    for (int i = 0; i < 4; i++)
#pragma unroll
        for (int j = 0; j < 4; j++)
#pragma unroll
            for (int q = 0; q < 4; q++) acc[i][j][q] = 0.0f;

    // prime: B fragments for kbp = 0
    uint4 bfc[4];
#pragma unroll
    for (int j = 0; j < 4; j++)
        bfc[j] = __ldg(Bbase + ((j * 32 + 0) << 5));

#pragma unroll 1
    for (int kbp = 0; kbp < 32; kbp++) {
        // prefetch next B (L2-latency load, hidden under this iteration's mma)
        uint4 bfn[4];
        int kn = (kbp + 1) & 31;                 // wraps on last iter (harmless re-load)
#pragma unroll
        for (int j = 0; j < 4; j++)
            bfn[j] = __ldg(Bbase + ((j * 32 + kn) << 5));

        // half 0: load A(kb=2*kbp), mma with bfc even-half
        uint4 af[4];
#pragma unroll
        for (int i = 0; i < 4; i++)
            af[i] = __ldg(Abase + ((i * 64 + 2 * kbp) << 5));
#pragma unroll
        for (int i = 0; i < 4; i++)
#pragma unroll
            for (int j = 0; j < 4; j++)
                mma_bf16(acc[i][j], af[i].x, af[i].y, af[i].z, af[i].w,
                         bfc[j].x, bfc[j].y);

        // half 1: load A(kb=2*kbp+1), mma with bfc odd-half
#pragma unroll
        for (int i = 0; i < 4; i++)
            af[i] = __ldg(Abase + ((i * 64 + 2 * kbp + 1) << 5));
#pragma unroll
        for (int i = 0; i < 4; i++)
#pragma unroll
            for (int j = 0; j < 4; j++)
                mma_bf16(acc[i][j], af[i].x, af[i].y, af[i].z, af[i].w,
                         bfc[j].z, bfc[j].w);

#pragma unroll
        for (int j = 0; j < 4; j++) bfc[j] = bfn[j];
    }

    // ---------------- fused epilogue ----------------
    int g = lane >> 2, t4 = lane & 3;
#pragma unroll
    for (int i = 0; i < 4; i++) {
        int r0 = m0 + wm * 64 + i * 16 + g;
        float sx0 = g_xs[r0];
        float sx1 = g_xs[r0 + 8];
        float* o0 = out + (size_t)r0 * OUT_F + n0;
        float* o1 = o0 + (size_t)8 * OUT_F;
#pragma unroll
        for (int j = 0; j < 4; j++) {
            int c = wn * 32 + j * 8 + t4 * 2;
            float w0 = g_ws[n0 + c], w1 = g_ws[n0 + c + 1];
            float b0 = bias[n0 + c], b1 = bias[n0 + c + 1];
            float2 v0, v1;
            v0.x = acc[i][j][0] * sx0 * w0 + b0;
            v0.y = acc[i][j][1] * sx0 * w1 + b1;
            v1.x = acc[i][j][2] * sx1 * w0 + b0;
            v1.y = acc[i][j][3] * sx1 * w1 + b1;
            *(float2*)(o0 + c) = v0;
            *(float2*)(o1 + c) = v1;
        }
    }
}

// ---------------- launch ----------------
extern "C" void kernel_launch(void* const* d_in, const int* in_sizes, int n_in,
                              void* d_out, int out_size) {
    const float* x    = (const float*)d_in[0];
    const float* w    = (const float*)d_in[1];
    const float* bias = (const float*)d_in[2];
    float* out = (float*)d_out;
    int tokens = in_sizes[0] / IN_F;

    int qBlocks = tokens / 16;
    prep_kernel<<<qBlocks + OUT_F / 16, 512>>>(x, w, qBlocks);

    int mtiles = tokens / TILE_M;
    onebit_gemm_kernel<<<mtiles * (OUT_F / TILE_N), 512>>>(bias, out);
}

// round 8
// speedup vs baseline: 1.1487x; 1.1487x over previous
#include <cuda_runtime.h>
#include <cuda_fp16.h>
#include <cuda_bf16.h>
#include <cstdint>
#include <cstddef>

// ---------------- problem constants ----------------
#define IN_F   1024
#define OUT_F  1024
#define MAX_TOKENS 32768
#define TILE_M 256
#define TILE_N 128

#define SM_STRIDE 2064    // prep-kernel smem row pad

// GEMM pipeline: B staged in smem, 4 chunks x 8 kbp, double buffered
#define KBP_CH   8
#define NCHUNK   4                                   // 32 kbp total
#define B_CH_U4  (16 * KBP_CH * 32)                  // uint4 units per chunk = 4096
#define B_CH_BYTES (B_CH_U4 * 16)                    // 64 KB
#define GEMM_SMEM (2 * B_CH_BYTES)                   // 128 KB

// ---------------- scratch: bf16 fragment-major operand layouts ----------------
// g_xa: [mg = token/16][kb = 64][lane = 32][16B = {a0,a1,a2,a3}]
__device__ __align__(16) __nv_bfloat16 g_xa[(size_t)MAX_TOKENS * IN_F];
__device__ float g_xs[MAX_TOKENS];
// g_wb: [ng = ocol/8][kbp = 32][lane = 32][16B = {b0 even kb, b1 even, b0 odd, b1 odd}]
__device__ __align__(16) __nv_bfloat16 g_wb[(size_t)OUT_F * IN_F];
__device__ float g_ws[OUT_F];

// ---------------- helpers ----------------
static __device__ __forceinline__ void mma_bf16(float* c, uint32_t a0, uint32_t a1,
                                                uint32_t a2, uint32_t a3,
                                                uint32_t b0, uint32_t b1) {
    asm volatile(
        "mma.sync.aligned.m16n8k16.row.col.f32.bf16.bf16.f32 "
        "{%0,%1,%2,%3}, {%4,%5,%6,%7}, {%8,%9}, {%0,%1,%2,%3};"
        : "+f"(c[0]), "+f"(c[1]), "+f"(c[2]), "+f"(c[3])
        : "r"(a0), "r"(a1), "r"(a2), "r"(a3), "r"(b0), "r"(b1));
}
static __device__ __forceinline__ uint32_t bf16x2(float lo, float hi) {
    return (uint32_t)__bfloat16_as_ushort(__float2bfloat16_rn(lo))
         | ((uint32_t)__bfloat16_as_ushort(__float2bfloat16_rn(hi)) << 16);
}
static __device__ __forceinline__ uint32_t smem_u32(const void* p) {
    uint32_t a;
    asm("{ .reg .u64 t; cvta.to.shared.u64 t, %1; cvt.u32.u64 %0, t; }" : "=r"(a) : "l"(p));
    return a;
}
static __device__ __forceinline__ void cp16(uint32_t s, const void* g) {
    asm volatile("cp.async.cg.shared.global [%0], [%1], 16;" :: "r"(s), "l"(g));
}
static __device__ __forceinline__ void lds128(uint4& v, uint32_t addr) {
    asm volatile("ld.shared.v4.u32 {%0,%1,%2,%3}, [%4];"
                 : "=r"(v.x), "=r"(v.y), "=r"(v.z), "=r"(v.w) : "r"(addr));
}

// ---------------- fused prep kernel (unchanged from round 6) ----------------
__global__ void __launch_bounds__(512) prep_kernel(const float* __restrict__ x,
                                                   const float* __restrict__ w,
                                                   int qBlocks) {
    __shared__ int8_t sm[16 * SM_STRIDE];
    int tid = threadIdx.x, warp = tid >> 5, lane = tid & 31;

    if ((int)blockIdx.x < qBlocks) {
        int mg = blockIdx.x;
        int t = mg * 16 + warp;
        const float4* xr = (const float4*)(x + (size_t)t * IN_F);
        float4 v[8];
        float m = 0.0f;
#pragma unroll
        for (int i = 0; i < 8; i++) {
            v[i] = xr[lane + 32 * i];
            m = fmaxf(m, fmaxf(fmaxf(fabsf(v[i].x), fabsf(v[i].y)),
                               fmaxf(fabsf(v[i].z), fabsf(v[i].w))));
        }
#pragma unroll
        for (int o = 16; o > 0; o >>= 1) m = fmaxf(m, __shfl_xor_sync(0xFFFFFFFFu, m, o));
        float scale = __fdiv_rn(fmaxf(m, 1e-8f), 127.0f);

#pragma unroll
        for (int i = 0; i < 8; i++) {
            float q0 = fminf(fmaxf(rintf(__fdiv_rn(v[i].x, scale)), -128.0f), 127.0f);
            float q1 = fminf(fmaxf(rintf(__fdiv_rn(v[i].y, scale)), -128.0f), 127.0f);
            float q2 = fminf(fmaxf(rintf(__fdiv_rn(v[i].z, scale)), -128.0f), 127.0f);
            float q3 = fminf(fmaxf(rintf(__fdiv_rn(v[i].w, scale)), -128.0f), 127.0f);
            uint2 pr = make_uint2(bf16x2(q0, q1), bf16x2(q2, q3));
            *(uint2*)(sm + warp * SM_STRIDE + 8 * lane + 256 * i) = pr;
        }
        if (lane == 0) g_xs[t] = scale;
        __syncthreads();

#pragma unroll
        for (int it = 0; it < 4; it++) {
            int u = tid + it * 512;
            int kb = u >> 5, l2 = u & 31;
            int g = l2 >> 2, t4 = l2 & 3;
            int bo = kb * 32 + t4 * 4;
            uint4 f;
            f.x = *(const uint32_t*)(sm + g * SM_STRIDE + bo);
            f.y = *(const uint32_t*)(sm + (g + 8) * SM_STRIDE + bo);
            f.z = *(const uint32_t*)(sm + g * SM_STRIDE + bo + 16);
            f.w = *(const uint32_t*)(sm + (g + 8) * SM_STRIDE + bo + 16);
            *(uint4*)((int8_t*)g_xa + ((((size_t)mg * 64 + kb) << 5) + l2) * 16) = f;
        }
    } else {
        int wb = blockIdx.x - qBlocks;
        int o = wb * 16 + warp;
        const float4* wr = (const float4*)(w + (size_t)o * IN_F);
        float am[8];
#pragma unroll
        for (int i = 0; i < 8; i++) {
            float4 v = wr[lane + 32 * i];
            uint2 pr;
            pr.x = (((v.x > 0.0f) ? 0x3F80u : 0xBF80u))
                 | (((v.y > 0.0f) ? 0x3F80u : 0xBF80u) << 16);
            pr.y = (((v.z > 0.0f) ? 0x3F80u : 0xBF80u))
                 | (((v.w > 0.0f) ? 0x3F80u : 0xBF80u) << 16);
            *(uint2*)(sm + warp * SM_STRIDE + 8 * lane + 256 * i) = pr;
            am[i] = fmaxf(fmaxf(fabsf(v.x), fabsf(v.y)), fmaxf(fabsf(v.z), fabsf(v.w)));
        }
#pragma unroll
        for (int i = 0; i < 8; i++)
#pragma unroll
            for (int off = 16; off > 0; off >>= 1)
                am[i] = fmaxf(am[i], __shfl_xor_sync(0xFFFFFFFFu, am[i], off));
        if (lane == 0) {
            float s = 0.0f;
#pragma unroll
            for (int i = 0; i < 8; i++)
                s += __half2float(__float2half_rn(fmaxf(am[i], 1e-8f)));
            g_ws[o] = s * 0.125f;
        }
        __syncthreads();

#pragma unroll
        for (int it = 0; it < 4; it++) {
            int u = tid + it * 512;
            int nh = u >> 10, kbp = (u >> 5) & 31, l2 = u & 31;
            int c = l2 >> 2, t4 = l2 & 3;
            int row = nh * 8 + c;
            int bo = kbp * 64 + t4 * 4;
            uint4 f;
            f.x = *(const uint32_t*)(sm + row * SM_STRIDE + bo);
            f.y = *(const uint32_t*)(sm + row * SM_STRIDE + bo + 16);
            f.z = *(const uint32_t*)(sm + row * SM_STRIDE + bo + 32);
            f.w = *(const uint32_t*)(sm + row * SM_STRIDE + bo + 48);
            int ng = wb * 2 + nh;
            *(uint4*)((int8_t*)g_wb + ((((size_t)ng * 32 + kbp) << 5) + l2) * 16) = f;
        }
    }
}

// ---------------- GEMM: A via LDG, B via cp.async double-buffered smem ----------------
__global__ void __launch_bounds__(512, 1)
onebit_gemm_kernel(const float* __restrict__ bias, float* __restrict__ out) {
    extern __shared__ char smem[];
    uint32_t SB = smem_u32(smem);

    int tid = threadIdx.x, warp = tid >> 5, lane = tid & 31;
    int wm = warp >> 2;            // 0..3 -> 64-row slab of 256
    int wn = warp & 3;             // 0..3 -> 32-col slab of 128
    int n_blk = blockIdx.x & 7;
    int m_blk = blockIdx.x >> 3;
    int m0 = m_blk * TILE_M, n0 = n_blk * TILE_N;

    int mgB = m_blk * 16 + wm * 4;
    int ngB0 = n_blk * 16;                      // CTA's first n-group

    const uint4* A = (const uint4*)g_xa;        // [(mg*64 + kb)*32 + lane]
    const uint4* Bg = (const uint4*)g_wb;       // [(ng*32 + kbp)*32 + lane]

    // cp.async of one B chunk: 4096 uint4 units over 512 threads (8 each)
    auto stage_chunk = [&](int c) {
        uint32_t dst = SB + (uint32_t)(c & 1) * B_CH_BYTES;
#pragma unroll
        for (int it = 0; it < 8; it++) {
            int u = tid + it * 512;
            int ngl = u >> 8;                   // 0..15
            int kbl = (u >> 5) & 7;             // 0..7
            int l2 = u & 31;
            cp16(dst + (uint32_t)u * 16,
                 Bg + ((((size_t)(ngB0 + ngl)) * 32 + c * KBP_CH + kbl) << 5) + l2);
        }
        asm volatile("cp.async.commit_group;" ::: "memory");
    };

    stage_chunk(0);

    float acc[4][4][4];
#pragma unroll
    for (int i = 0; i < 4; i++)
#pragma unroll
        for (int j = 0; j < 4; j++)
#pragma unroll
            for (int q = 0; q < 4; q++) acc[i][j][q] = 0.0f;

    // warp's B base within a chunk buffer: groups wn*4 .. wn*4+3
    uint32_t bOff = (uint32_t)(((wn * 4) * KBP_CH) * 32 + lane) * 16;

#pragma unroll 1
    for (int c = 0; c < NCHUNK; c++) {
        if (c + 1 < NCHUNK) {
            stage_chunk(c + 1);
            asm volatile("cp.async.wait_group 1;" ::: "memory");
        } else {
            asm volatile("cp.async.wait_group 0;" ::: "memory");
        }
        __syncthreads();

        uint32_t bBuf = SB + (uint32_t)(c & 1) * B_CH_BYTES + bOff;

#pragma unroll
        for (int kbl = 0; kbl < KBP_CH; kbl++) {
            int kb0 = (c * KBP_CH + kbl) * 2;
            uint4 bf[4];
#pragma unroll
            for (int j = 0; j < 4; j++)
                lds128(bf[j], bBuf + (uint32_t)((j * KBP_CH + kbl) * 32) * 16);

            uint4 af[4];
#pragma unroll
            for (int i = 0; i < 4; i++)
                af[i] = A[(((size_t)(mgB + i) * 64 + kb0) << 5) + lane];
#pragma unroll
            for (int i = 0; i < 4; i++)
#pragma unroll
                for (int j = 0; j < 4; j++)
                    mma_bf16(acc[i][j], af[i].x, af[i].y, af[i].z, af[i].w,
                             bf[j].x, bf[j].y);

#pragma unroll
            for (int i = 0; i < 4; i++)
                af[i] = A[(((size_t)(mgB + i) * 64 + kb0 + 1) << 5) + lane];
#pragma unroll
            for (int i = 0; i < 4; i++)
#pragma unroll
                for (int j = 0; j < 4; j++)
                    mma_bf16(acc[i][j], af[i].x, af[i].y, af[i].z, af[i].w,
                             bf[j].z, bf[j].w);
        }
        __syncthreads();
    }

    // ---------------- fused epilogue ----------------
    int g = lane >> 2, t4 = lane & 3;
#pragma unroll
    for (int i = 0; i < 4; i++) {
        int r0 = m0 + wm * 64 + i * 16 + g;
        float sx0 = g_xs[r0];
        float sx1 = g_xs[r0 + 8];
        float* o0 = out + (size_t)r0 * OUT_F + n0;
        float* o1 = o0 + (size_t)8 * OUT_F;
#pragma unroll
        for (int j = 0; j < 4; j++) {
            int c = wn * 32 + j * 8 + t4 * 2;
            float w0 = g_ws[n0 + c], w1 = g_ws[n0 + c + 1];
            float b0 = bias[n0 + c], b1 = bias[n0 + c + 1];
            float2 v0, v1;
            v0.x = acc[i][j][0] * sx0 * w0 + b0;
            v0.y = acc[i][j][1] * sx0 * w1 + b1;
            v1.x = acc[i][j][2] * sx1 * w0 + b0;
            v1.y = acc[i][j][3] * sx1 * w1 + b1;
            *(float2*)(o0 + c) = v0;
            *(float2*)(o1 + c) = v1;
        }
    }
}

// ---------------- launch ----------------
extern "C" void kernel_launch(void* const* d_in, const int* in_sizes, int n_in,
                              void* d_out, int out_size) {
    const float* x    = (const float*)d_in[0];
    const float* w    = (const float*)d_in[1];
    const float* bias = (const float*)d_in[2];
    float* out = (float*)d_out;
    int tokens = in_sizes[0] / IN_F;

    int qBlocks = tokens / 16;
    prep_kernel<<<qBlocks + OUT_F / 16, 512>>>(x, w, qBlocks);

    cudaFuncSetAttribute(onebit_gemm_kernel,
                         cudaFuncAttributeMaxDynamicSharedMemorySize, GEMM_SMEM);
    int mtiles = tokens / TILE_M;
    onebit_gemm_kernel<<<mtiles * (OUT_F / TILE_N), 512, GEMM_SMEM>>>(bias, out);
}

// round 9
// speedup vs baseline: 1.5341x; 1.3354x over previous
#include <cuda_runtime.h>
#include <cuda_fp16.h>
#include <cuda_bf16.h>
#include <cstdint>
#include <cstddef>

// ---------------- problem constants ----------------
#define IN_F   1024
#define OUT_F  1024
#define MAX_TOKENS 32768
#define TILE_M 256
#define TILE_N 128

#define SM_STRIDE 2064    // prep-kernel smem row pad

// GEMM pipeline: A+B staged in smem, chunk = 8 kb (4 kbp), double buffered
#define KB_CH    8                                   // kb per chunk
#define NCHUNK   8                                   // 64 kb total
#define A_CH_BYTES (16 * KB_CH * 32 * 16)            // 65536
#define B_CH_BYTES (16 * (KB_CH/2) * 32 * 16)       // 32768
#define STAGE_BYTES (A_CH_BYTES + B_CH_BYTES)        // 98304
#define GEMM_SMEM (2 * STAGE_BYTES)                  // 196608

// ---------------- scratch: bf16 fragment-major operand layouts ----------------
// g_xa: [mg = token/16][kb = 64][lane = 32][16B = {a0,a1,a2,a3}]
__device__ __align__(16) __nv_bfloat16 g_xa[(size_t)MAX_TOKENS * IN_F];
__device__ float g_xs[MAX_TOKENS];
// g_wb: [ng = ocol/8][kbp = 32][lane = 32][16B = {b0 even kb, b1 even, b0 odd, b1 odd}]
__device__ __align__(16) __nv_bfloat16 g_wb[(size_t)OUT_F * IN_F];
__device__ float g_ws[OUT_F];

// ---------------- helpers ----------------
static __device__ __forceinline__ void mma_bf16(float* c, uint32_t a0, uint32_t a1,
                                                uint32_t a2, uint32_t a3,
                                                uint32_t b0, uint32_t b1) {
    asm volatile(
        "mma.sync.aligned.m16n8k16.row.col.f32.bf16.bf16.f32 "
        "{%0,%1,%2,%3}, {%4,%5,%6,%7}, {%8,%9}, {%0,%1,%2,%3};"
        : "+f"(c[0]), "+f"(c[1]), "+f"(c[2]), "+f"(c[3])
        : "r"(a0), "r"(a1), "r"(a2), "r"(a3), "r"(b0), "r"(b1));
}
static __device__ __forceinline__ uint32_t bf16x2(float lo, float hi) {
    return (uint32_t)__bfloat16_as_ushort(__float2bfloat16_rn(lo))
         | ((uint32_t)__bfloat16_as_ushort(__float2bfloat16_rn(hi)) << 16);
}
static __device__ __forceinline__ uint32_t smem_u32(const void* p) {
    uint32_t a;
    asm("{ .reg .u64 t; cvta.to.shared.u64 t, %1; cvt.u32.u64 %0, t; }" : "=r"(a) : "l"(p));
    return a;
}
static __device__ __forceinline__ void cp16(uint32_t s, const void* g) {
    asm volatile("cp.async.cg.shared.global [%0], [%1], 16;" :: "r"(s), "l"(g));
}
static __device__ __forceinline__ void lds128(uint4& v, uint32_t addr) {
    asm volatile("ld.shared.v4.u32 {%0,%1,%2,%3}, [%4];"
                 : "=r"(v.x), "=r"(v.y), "=r"(v.z), "=r"(v.w) : "r"(addr));
}

// ---------------- fused prep kernel (unchanged, proven) ----------------
__global__ void __launch_bounds__(512) prep_kernel(const float* __restrict__ x,
                                                   const float* __restrict__ w,
                                                   int qBlocks) {
    __shared__ int8_t sm[16 * SM_STRIDE];
    int tid = threadIdx.x, warp = tid >> 5, lane = tid & 31;

    if ((int)blockIdx.x < qBlocks) {
        int mg = blockIdx.x;
        int t = mg * 16 + warp;
        const float4* xr = (const float4*)(x + (size_t)t * IN_F);
        float4 v[8];
        float m = 0.0f;
#pragma unroll
        for (int i = 0; i < 8; i++) {
            v[i] = xr[lane + 32 * i];
            m = fmaxf(m, fmaxf(fmaxf(fabsf(v[i].x), fabsf(v[i].y)),
                               fmaxf(fabsf(v[i].z), fabsf(v[i].w))));
        }
#pragma unroll
        for (int o = 16; o > 0; o >>= 1) m = fmaxf(m, __shfl_xor_sync(0xFFFFFFFFu, m, o));
        float scale = __fdiv_rn(fmaxf(m, 1e-8f), 127.0f);

#pragma unroll
        for (int i = 0; i < 8; i++) {
            float q0 = fminf(fmaxf(rintf(__fdiv_rn(v[i].x, scale)), -128.0f), 127.0f);
            float q1 = fminf(fmaxf(rintf(__fdiv_rn(v[i].y, scale)), -128.0f), 127.0f);
            float q2 = fminf(fmaxf(rintf(__fdiv_rn(v[i].z, scale)), -128.0f), 127.0f);
            float q3 = fminf(fmaxf(rintf(__fdiv_rn(v[i].w, scale)), -128.0f), 127.0f);
            uint2 pr = make_uint2(bf16x2(q0, q1), bf16x2(q2, q3));
            *(uint2*)(sm + warp * SM_STRIDE + 8 * lane + 256 * i) = pr;
        }
        if (lane == 0) g_xs[t] = scale;
        __syncthreads();

#pragma unroll
        for (int it = 0; it < 4; it++) {
            int u = tid + it * 512;
            int kb = u >> 5, l2 = u & 31;
            int g = l2 >> 2, t4 = l2 & 3;
            int bo = kb * 32 + t4 * 4;
            uint4 f;
            f.x = *(const uint32_t*)(sm + g * SM_STRIDE + bo);
            f.y = *(const uint32_t*)(sm + (g + 8) * SM_STRIDE + bo);
            f.z = *(const uint32_t*)(sm + g * SM_STRIDE + bo + 16);
            f.w = *(const uint32_t*)(sm + (g + 8) * SM_STRIDE + bo + 16);
            *(uint4*)((int8_t*)g_xa + ((((size_t)mg * 64 + kb) << 5) + l2) * 16) = f;
        }
    } else {
        int wb = blockIdx.x - qBlocks;
        int o = wb * 16 + warp;
        const float4* wr = (const float4*)(w + (size_t)o * IN_F);
        float am[8];
#pragma unroll
        for (int i = 0; i < 8; i++) {
            float4 v = wr[lane + 32 * i];
            uint2 pr;
            pr.x = (((v.x > 0.0f) ? 0x3F80u : 0xBF80u))
                 | (((v.y > 0.0f) ? 0x3F80u : 0xBF80u) << 16);
            pr.y = (((v.z > 0.0f) ? 0x3F80u : 0xBF80u))
                 | (((v.w > 0.0f) ? 0x3F80u : 0xBF80u) << 16);
            *(uint2*)(sm + warp * SM_STRIDE + 8 * lane + 256 * i) = pr;
            am[i] = fmaxf(fmaxf(fabsf(v.x), fabsf(v.y)), fmaxf(fabsf(v.z), fabsf(v.w)));
        }
#pragma unroll
        for (int i = 0; i < 8; i++)
#pragma unroll
            for (int off = 16; off > 0; off >>= 1)
                am[i] = fmaxf(am[i], __shfl_xor_sync(0xFFFFFFFFu, am[i], off));
        if (lane == 0) {
            float s = 0.0f;
#pragma unroll
            for (int i = 0; i < 8; i++)
                s += __half2float(__float2half_rn(fmaxf(am[i], 1e-8f)));
            g_ws[o] = s * 0.125f;
        }
        __syncthreads();

#pragma unroll
        for (int it = 0; it < 4; it++) {
            int u = tid + it * 512;
            int nh = u >> 10, kbp = (u >> 5) & 31, l2 = u & 31;
            int c = l2 >> 2, t4 = l2 & 3;
            int row = nh * 8 + c;
            int bo = kbp * 64 + t4 * 4;
            uint4 f;
            f.x = *(const uint32_t*)(sm + row * SM_STRIDE + bo);
            f.y = *(const uint32_t*)(sm + row * SM_STRIDE + bo + 16);
            f.z = *(const uint32_t*)(sm + row * SM_STRIDE + bo + 32);
            f.w = *(const uint32_t*)(sm + row * SM_STRIDE + bo + 48);
            int ng = wb * 2 + nh;
            *(uint4*)((int8_t*)g_wb + ((((size_t)ng * 32 + kbp) << 5) + l2) * 16) = f;
        }
    }
}

// ---------------- GEMM: A+B via cp.async double-buffered smem ----------------
__global__ void __launch_bounds__(512, 1)
onebit_gemm_kernel(const float* __restrict__ bias, float* __restrict__ out) {
    extern __shared__ char smem[];
    uint32_t SB = smem_u32(smem);

    int tid = threadIdx.x, warp = tid >> 5, lane = tid & 31;
    int wm = warp >> 2;            // 0..3 -> 64-row slab of 256
    int wn = warp & 3;             // 0..3 -> 32-col slab of 128
    int n_blk = blockIdx.x & 7;
    int m_blk = blockIdx.x >> 3;
    int m0 = m_blk * TILE_M, n0 = n_blk * TILE_N;

    int mgB0 = m_blk * 16;                      // CTA's first m16 group
    int ngB0 = n_blk * 16;                      // CTA's first n8 group

    const uint4* Ag = (const uint4*)g_xa;       // [(mg*64 + kb)*32 + lane]
    const uint4* Bg = (const uint4*)g_wb;       // [(ng*32 + kbp)*32 + lane]

    // stage one chunk (8 kb of A, 4 kbp of B) into buffer c&1
    auto stage_chunk = [&](int c) {
        uint32_t dst = SB + (uint32_t)(c & 1) * STAGE_BYTES;
        // A: 4096 uint4 units; smem order [mg][kbl][lane]
#pragma unroll
        for (int it = 0; it < 8; it++) {
            int u = tid + it * 512;
            int mg = u >> 8, kbl = (u >> 5) & 7, l2 = u & 31;
            cp16(dst + (uint32_t)u * 16,
                 Ag + ((((size_t)(mgB0 + mg)) * 64 + c * KB_CH + kbl) << 5) + l2);
        }
        // B: 2048 uint4 units; smem order [ng][kbpl][lane]
#pragma unroll
        for (int it = 0; it < 4; it++) {
            int u = tid + it * 512;
            int ng = u >> 7, kbpl = (u >> 5) & 3, l2 = u & 31;
            cp16(dst + A_CH_BYTES + (uint32_t)u * 16,
                 Bg + ((((size_t)(ngB0 + ng)) * 32 + c * (KB_CH / 2) + kbpl) << 5) + l2);
        }
        asm volatile("cp.async.commit_group;" ::: "memory");
    };

    stage_chunk(0);

    float acc[4][4][4];
#pragma unroll
    for (int i = 0; i < 4; i++)
#pragma unroll
        for (int j = 0; j < 4; j++)
#pragma unroll
            for (int q = 0; q < 4; q++) acc[i][j][q] = 0.0f;

#pragma unroll 1
    for (int c = 0; c < NCHUNK; c++) {
        asm volatile("cp.async.wait_group 0;" ::: "memory");
        __syncthreads();
        if (c + 1 < NCHUNK) stage_chunk(c + 1);   // overlaps compute of chunk c

        uint32_t buf = SB + (uint32_t)(c & 1) * STAGE_BYTES;
        uint32_t aW = buf + (uint32_t)(((wm * 4) * KB_CH) * 32 + lane) * 16;
        uint32_t bW = buf + A_CH_BYTES
                    + (uint32_t)(((wn * 4) * (KB_CH / 2)) * 32 + lane) * 16;

#pragma unroll
        for (int kbpl = 0; kbpl < KB_CH / 2; kbpl++) {
            uint4 bf[4];
#pragma unroll
            for (int j = 0; j < 4; j++)
                lds128(bf[j], bW + (uint32_t)((j * (KB_CH / 2) + kbpl) * 32) * 16);

            uint4 af[4];
#pragma unroll
            for (int i = 0; i < 4; i++)
                lds128(af[i], aW + (uint32_t)((i * KB_CH + 2 * kbpl) * 32) * 16);
#pragma unroll
            for (int i = 0; i < 4; i++)
#pragma unroll
                for (int j = 0; j < 4; j++)
                    mma_bf16(acc[i][j], af[i].x, af[i].y, af[i].z, af[i].w,
                             bf[j].x, bf[j].y);

#pragma unroll
            for (int i = 0; i < 4; i++)
                lds128(af[i], aW + (uint32_t)((i * KB_CH + 2 * kbpl + 1) * 32) * 16);
#pragma unroll
            for (int i = 0; i < 4; i++)
#pragma unroll
                for (int j = 0; j < 4; j++)
                    mma_bf16(acc[i][j], af[i].x, af[i].y, af[i].z, af[i].w,
                             bf[j].z, bf[j].w);
        }
        __syncthreads();
    }

    // ---------------- fused epilogue ----------------
    int g = lane >> 2, t4 = lane & 3;
#pragma unroll
    for (int i = 0; i < 4; i++) {
        int r0 = m0 + wm * 64 + i * 16 + g;
        float sx0 = g_xs[r0];
        float sx1 = g_xs[r0 + 8];
        float* o0 = out + (size_t)r0 * OUT_F + n0;
        float* o1 = o0 + (size_t)8 * OUT_F;
#pragma unroll
        for (int j = 0; j < 4; j++) {
            int c = wn * 32 + j * 8 + t4 * 2;
            float w0 = g_ws[n0 + c], w1 = g_ws[n0 + c + 1];
            float b0 = bias[n0 + c], b1 = bias[n0 + c + 1];
            float2 v0, v1;
            v0.x = acc[i][j][0] * sx0 * w0 + b0;
            v0.y = acc[i][j][1] * sx0 * w1 + b1;
            v1.x = acc[i][j][2] * sx1 * w0 + b0;
            v1.y = acc[i][j][3] * sx1 * w1 + b1;
            *(float2*)(o0 + c) = v0;
            *(float2*)(o1 + c) = v1;
        }
    }
}

// ---------------- launch ----------------
extern "C" void kernel_launch(void* const* d_in, const int* in_sizes, int n_in,
                              void* d_out, int out_size) {
    const float* x    = (const float*)d_in[0];
    const float* w    = (const float*)d_in[1];
    const float* bias = (const float*)d_in[2];
    float* out = (float*)d_out;
    int tokens = in_sizes[0] / IN_F;

    int qBlocks = tokens / 16;
    prep_kernel<<<qBlocks + OUT_F / 16, 512>>>(x, w, qBlocks);

    cudaFuncSetAttribute(onebit_gemm_kernel,
                         cudaFuncAttributeMaxDynamicSharedMemorySize, GEMM_SMEM);
    int mtiles = tokens / TILE_M;
    onebit_gemm_kernel<<<mtiles * (OUT_F / TILE_N), 512, GEMM_SMEM>>>(bias, out);
}

// round 10
// speedup vs baseline: 1.5447x; 1.0069x over previous
#include <cuda_runtime.h>
#include <cuda_fp16.h>
#include <cuda_bf16.h>
#include <cstdint>
#include <cstddef>

// ---------------- problem constants ----------------
#define IN_F   1024
#define OUT_F  1024
#define MAX_TOKENS 32768
#define TILE_M 256
#define TILE_N 128

#define SM_STRIDE 2064    // prep-kernel smem row pad

// GEMM pipeline: A+B staged in smem, chunk = 4 kb (2 kbp), 3-stage
#define KB_CH    4                                   // kb per chunk
#define NCHUNK   16                                  // 64 kb total
#define NSTAGE   3
#define A_CH_BYTES (16 * KB_CH * 32 * 16)            // 32768
#define B_CH_BYTES (16 * (KB_CH/2) * 32 * 16)        // 16384
#define STAGE_BYTES (A_CH_BYTES + B_CH_BYTES)        // 49152
#define GEMM_SMEM (NSTAGE * STAGE_BYTES)             // 147456

// ---------------- scratch: bf16 fragment-major operand layouts ----------------
// g_xa: [mg = token/16][kb = 64][lane = 32][16B = {a0,a1,a2,a3}]
__device__ __align__(16) __nv_bfloat16 g_xa[(size_t)MAX_TOKENS * IN_F];
__device__ float g_xs[MAX_TOKENS];
// g_wb: [ng = ocol/8][kbp = 32][lane = 32][16B = {b0 even kb, b1 even, b0 odd, b1 odd}]
__device__ __align__(16) __nv_bfloat16 g_wb[(size_t)OUT_F * IN_F];
__device__ float g_ws[OUT_F];

// ---------------- helpers ----------------
static __device__ __forceinline__ void mma_bf16(float* c, uint32_t a0, uint32_t a1,
                                                uint32_t a2, uint32_t a3,
                                                uint32_t b0, uint32_t b1) {
    asm volatile(
        "mma.sync.aligned.m16n8k16.row.col.f32.bf16.bf16.f32 "
        "{%0,%1,%2,%3}, {%4,%5,%6,%7}, {%8,%9}, {%0,%1,%2,%3};"
        : "+f"(c[0]), "+f"(c[1]), "+f"(c[2]), "+f"(c[3])
        : "r"(a0), "r"(a1), "r"(a2), "r"(a3), "r"(b0), "r"(b1));
}
static __device__ __forceinline__ uint32_t bf16x2(float lo, float hi) {
    return (uint32_t)__bfloat16_as_ushort(__float2bfloat16_rn(lo))
         | ((uint32_t)__bfloat16_as_ushort(__float2bfloat16_rn(hi)) << 16);
}
static __device__ __forceinline__ uint32_t smem_u32(const void* p) {
    uint32_t a;
    asm("{ .reg .u64 t; cvta.to.shared.u64 t, %1; cvt.u32.u64 %0, t; }" : "=r"(a) : "l"(p));
    return a;
}
static __device__ __forceinline__ void cp16(uint32_t s, const void* g) {
    asm volatile("cp.async.cg.shared.global [%0], [%1], 16;" :: "r"(s), "l"(g));
}
static __device__ __forceinline__ void lds128(uint4& v, uint32_t addr) {
    asm volatile("ld.shared.v4.u32 {%0,%1,%2,%3}, [%4];"
                 : "=r"(v.x), "=r"(v.y), "=r"(v.z), "=r"(v.w) : "r"(addr));
}

// ---------------- fused prep kernel (unchanged, proven) ----------------
__global__ void __launch_bounds__(512) prep_kernel(const float* __restrict__ x,
                                                   const float* __restrict__ w,
                                                   int qBlocks) {
    __shared__ int8_t sm[16 * SM_STRIDE];
    int tid = threadIdx.x, warp = tid >> 5, lane = tid & 31;

    if ((int)blockIdx.x < qBlocks) {
        int mg = blockIdx.x;
        int t = mg * 16 + warp;
        const float4* xr = (const float4*)(x + (size_t)t * IN_F);
        float4 v[8];
        float m = 0.0f;
#pragma unroll
        for (int i = 0; i < 8; i++) {
            v[i] = xr[lane + 32 * i];
            m = fmaxf(m, fmaxf(fmaxf(fabsf(v[i].x), fabsf(v[i].y)),
                               fmaxf(fabsf(v[i].z), fabsf(v[i].w))));
        }
#pragma unroll
        for (int o = 16; o > 0; o >>= 1) m = fmaxf(m, __shfl_xor_sync(0xFFFFFFFFu, m, o));
        float scale = __fdiv_rn(fmaxf(m, 1e-8f), 127.0f);

#pragma unroll
        for (int i = 0; i < 8; i++) {
            float q0 = fminf(fmaxf(rintf(__fdiv_rn(v[i].x, scale)), -128.0f), 127.0f);
            float q1 = fminf(fmaxf(rintf(__fdiv_rn(v[i].y, scale)), -128.0f), 127.0f);
            float q2 = fminf(fmaxf(rintf(__fdiv_rn(v[i].z, scale)), -128.0f), 127.0f);
            float q3 = fminf(fmaxf(rintf(__fdiv_rn(v[i].w, scale)), -128.0f), 127.0f);
            uint2 pr = make_uint2(bf16x2(q0, q1), bf16x2(q2, q3));
            *(uint2*)(sm + warp * SM_STRIDE + 8 * lane + 256 * i) = pr;
        }
        if (lane == 0) g_xs[t] = scale;
        __syncthreads();

#pragma unroll
        for (int it = 0; it < 4; it++) {
            int u = tid + it * 512;
            int kb = u >> 5, l2 = u & 31;
            int g = l2 >> 2, t4 = l2 & 3;
            int bo = kb * 32 + t4 * 4;
            uint4 f;
            f.x = *(const uint32_t*)(sm + g * SM_STRIDE + bo);
            f.y = *(const uint32_t*)(sm + (g + 8) * SM_STRIDE + bo);
            f.z = *(const uint32_t*)(sm + g * SM_STRIDE + bo + 16);
            f.w = *(const uint32_t*)(sm + (g + 8) * SM_STRIDE + bo + 16);
            *(uint4*)((int8_t*)g_xa + ((((size_t)mg * 64 + kb) << 5) + l2) * 16) = f;
        }
    } else {
        int wb = blockIdx.x - qBlocks;
        int o = wb * 16 + warp;
        const float4* wr = (const float4*)(w + (size_t)o * IN_F);
        float am[8];
#pragma unroll
        for (int i = 0; i < 8; i++) {
            float4 v = wr[lane + 32 * i];
            uint2 pr;
            pr.x = (((v.x > 0.0f) ? 0x3F80u : 0xBF80u))
                 | (((v.y > 0.0f) ? 0x3F80u : 0xBF80u) << 16);
            pr.y = (((v.z > 0.0f) ? 0x3F80u : 0xBF80u))
                 | (((v.w > 0.0f) ? 0x3F80u : 0xBF80u) << 16);
            *(uint2*)(sm + warp * SM_STRIDE + 8 * lane + 256 * i) = pr;
            am[i] = fmaxf(fmaxf(fabsf(v.x), fabsf(v.y)), fmaxf(fabsf(v.z), fabsf(v.w)));
        }
#pragma unroll
        for (int i = 0; i < 8; i++)
#pragma unroll
            for (int off = 16; off > 0; off >>= 1)
                am[i] = fmaxf(am[i], __shfl_xor_sync(0xFFFFFFFFu, am[i], off));
        if (lane == 0) {
            float s = 0.0f;
#pragma unroll
            for (int i = 0; i < 8; i++)
                s += __half2float(__float2half_rn(fmaxf(am[i], 1e-8f)));
            g_ws[o] = s * 0.125f;
        }
        __syncthreads();

#pragma unroll
        for (int it = 0; it < 4; it++) {
            int u = tid + it * 512;
            int nh = u >> 10, kbp = (u >> 5) & 31, l2 = u & 31;
            int c = l2 >> 2, t4 = l2 & 3;
            int row = nh * 8 + c;
            int bo = kbp * 64 + t4 * 4;
            uint4 f;
            f.x = *(const uint32_t*)(sm + row * SM_STRIDE + bo);
            f.y = *(const uint32_t*)(sm + row * SM_STRIDE + bo + 16);
            f.z = *(const uint32_t*)(sm + row * SM_STRIDE + bo + 32);
            f.w = *(const uint32_t*)(sm + row * SM_STRIDE + bo + 48);
            int ng = wb * 2 + nh;
            *(uint4*)((int8_t*)g_wb + ((((size_t)ng * 32 + kbp) << 5) + l2) * 16) = f;
        }
    }
}

// ---------------- GEMM: 3-stage cp.async pipeline, 1 barrier per chunk ----------------
__global__ void __launch_bounds__(512, 1)
onebit_gemm_kernel(const float* __restrict__ bias, float* __restrict__ out) {
    extern __shared__ char smem[];
    uint32_t SB = smem_u32(smem);

    int tid = threadIdx.x, warp = tid >> 5, lane = tid & 31;
    int wm = warp >> 2;            // 0..3 -> 64-row slab of 256
    int wn = warp & 3;             // 0..3 -> 32-col slab of 128
    int n_blk = blockIdx.x & 7;
    int m_blk = blockIdx.x >> 3;
    int m0 = m_blk * TILE_M, n0 = n_blk * TILE_N;

    int mgB0 = m_blk * 16;
    int ngB0 = n_blk * 16;

    const uint4* Ag = (const uint4*)g_xa;       // [(mg*64 + kb)*32 + lane]
    const uint4* Bg = (const uint4*)g_wb;       // [(ng*32 + kbp)*32 + lane]

    // stage chunk c (4 kb of A, 2 kbp of B) into buffer (c % 3)
    auto stage_chunk = [&](int c) {
        uint32_t dst = SB + (uint32_t)(c % NSTAGE) * STAGE_BYTES;
        // A: 2048 uint4 units; smem order [mg][kbl][lane]
#pragma unroll
        for (int it = 0; it < 4; it++) {
            int u = tid + it * 512;
            int mg = u >> 7, kbl = (u >> 5) & 3, l2 = u & 31;
            cp16(dst + (uint32_t)u * 16,
                 Ag + ((((size_t)(mgB0 + mg)) * 64 + c * KB_CH + kbl) << 5) + l2);
        }
        // B: 1024 uint4 units; smem order [ng][kbpl][lane]
#pragma unroll
        for (int it = 0; it < 2; it++) {
            int u = tid + it * 512;
            int ng = u >> 6, kbpl = (u >> 5) & 1, l2 = u & 31;
            cp16(dst + A_CH_BYTES + (uint32_t)u * 16,
                 Bg + ((((size_t)(ngB0 + ng)) * 32 + c * (KB_CH / 2) + kbpl) << 5) + l2);
        }
        asm volatile("cp.async.commit_group;" ::: "memory");
    };

    stage_chunk(0);
    stage_chunk(1);

    float acc[4][4][4];
#pragma unroll
    for (int i = 0; i < 4; i++)
#pragma unroll
        for (int j = 0; j < 4; j++)
#pragma unroll
            for (int q = 0; q < 4; q++) acc[i][j][q] = 0.0f;

    uint32_t aWOff = (uint32_t)(((wm * 4) * KB_CH) * 32 + lane) * 16;
    uint32_t bWOff = (uint32_t)A_CH_BYTES
                   + (uint32_t)(((wn * 4) * (KB_CH / 2)) * 32 + lane) * 16;

#pragma unroll 1
    for (int c = 0; c < NCHUNK; c++) {
        // chunk c ready when at most 1 group (c+1) still outstanding
        asm volatile("cp.async.wait_group 1;" ::: "memory");
        __syncthreads();   // also guards buffer (c+2)%3 reuse: all warps done with chunk c-1

        uint32_t buf = SB + (uint32_t)(c % NSTAGE) * STAGE_BYTES;
        uint32_t aW = buf + aWOff;
        uint32_t bW = buf + bWOff;

#pragma unroll
        for (int kbpl = 0; kbpl < KB_CH / 2; kbpl++) {
            uint4 bf[4];
#pragma unroll
            for (int j = 0; j < 4; j++)
                lds128(bf[j], bW + (uint32_t)((j * (KB_CH / 2) + kbpl) * 32) * 16);

            uint4 af[4];
#pragma unroll
            for (int i = 0; i < 4; i++)
                lds128(af[i], aW + (uint32_t)((i * KB_CH + 2 * kbpl) * 32) * 16);
#pragma unroll
            for (int i = 0; i < 4; i++)
#pragma unroll
                for (int j = 0; j < 4; j++)
                    mma_bf16(acc[i][j], af[i].x, af[i].y, af[i].z, af[i].w,
                             bf[j].x, bf[j].y);

#pragma unroll
            for (int i = 0; i < 4; i++)
                lds128(af[i], aW + (uint32_t)((i * KB_CH + 2 * kbpl + 1) * 32) * 16);
#pragma unroll
            for (int i = 0; i < 4; i++)
#pragma unroll
                for (int j = 0; j < 4; j++)
                    mma_bf16(acc[i][j], af[i].x, af[i].y, af[i].z, af[i].w,
                             bf[j].z, bf[j].w);
        }

        if (c + 2 < NCHUNK) stage_chunk(c + 2);
    }

    // ---------------- fused epilogue ----------------
    int g = lane >> 2, t4 = lane & 3;
#pragma unroll
    for (int i = 0; i < 4; i++) {
        int r0 = m0 + wm * 64 + i * 16 + g;
        float sx0 = g_xs[r0];
        float sx1 = g_xs[r0 + 8];
        float* o0 = out + (size_t)r0 * OUT_F + n0;
        float* o1 = o0 + (size_t)8 * OUT_F;
#pragma unroll
        for (int j = 0; j < 4; j++) {
            int c = wn * 32 + j * 8 + t4 * 2;
            float w0 = g_ws[n0 + c], w1 = g_ws[n0 + c + 1];
            float b0 = bias[n0 + c], b1 = bias[n0 + c + 1];
            float2 v0, v1;
            v0.x = acc[i][j][0] * sx0 * w0 + b0;
            v0.y = acc[i][j][1] * sx0 * w1 + b1;
            v1.x = acc[i][j][2] * sx1 * w0 + b0;
            v1.y = acc[i][j][3] * sx1 * w1 + b1;
            *(float2*)(o0 + c) = v0;
            *(float2*)(o1 + c) = v1;
        }
    }
}

// ---------------- launch ----------------
extern "C" void kernel_launch(void* const* d_in, const int* in_sizes, int n_in,
                              void* d_out, int out_size) {
    const float* x    = (const float*)d_in[0];
    const float* w    = (const float*)d_in[1];
    const float* bias = (const float*)d_in[2];
    float* out = (float*)d_out;
    int tokens = in_sizes[0] / IN_F;

    int qBlocks = tokens / 16;
    prep_kernel<<<qBlocks + OUT_F / 16, 512>>>(x, w, qBlocks);

    cudaFuncSetAttribute(onebit_gemm_kernel,
                         cudaFuncAttributeMaxDynamicSharedMemorySize, GEMM_SMEM);
    int mtiles = tokens / TILE_M;
    onebit_gemm_kernel<<<mtiles * (OUT_F / TILE_N), 512, GEMM_SMEM>>>(bias, out);
}

// round 11
// speedup vs baseline: 1.5449x; 1.0001x over previous
#include <cuda_runtime.h>
#include <cuda_fp16.h>
#include <cuda_bf16.h>
#include <cstdint>
#include <cstddef>

// ---------------- problem constants ----------------
#define IN_F   1024
#define OUT_F  1024
#define MAX_TOKENS 32768
#define TILE_M 256
#define TILE_N 128

#define SM_STRIDE 2064    // prep-kernel smem row pad

// GEMM pipeline: chunk = 4 kb (2 kbp), 3-stage, persistent CTAs
#define KB_CH    4
#define CH_TILE  16                                  // chunks per tile (64 kb)
#define NSTAGE   3
#define A_CH_BYTES (16 * KB_CH * 32 * 16)            // 32768
#define B_CH_BYTES (16 * (KB_CH/2) * 32 * 16)        // 16384
#define STAGE_BYTES (A_CH_BYTES + B_CH_BYTES)        // 49152
#define GEMM_SMEM (NSTAGE * STAGE_BYTES)             // 147456
#define GRID_P   148

// ---------------- scratch: bf16 fragment-major operand layouts ----------------
__device__ __align__(16) __nv_bfloat16 g_xa[(size_t)MAX_TOKENS * IN_F];
__device__ float g_xs[MAX_TOKENS];
__device__ __align__(16) __nv_bfloat16 g_wb[(size_t)OUT_F * IN_F];
__device__ float g_ws[OUT_F];

// ---------------- helpers ----------------
static __device__ __forceinline__ void mma_bf16(float* c, uint32_t a0, uint32_t a1,
                                                uint32_t a2, uint32_t a3,
                                                uint32_t b0, uint32_t b1) {
    asm volatile(
        "mma.sync.aligned.m16n8k16.row.col.f32.bf16.bf16.f32 "
        "{%0,%1,%2,%3}, {%4,%5,%6,%7}, {%8,%9}, {%0,%1,%2,%3};"
        : "+f"(c[0]), "+f"(c[1]), "+f"(c[2]), "+f"(c[3])
        : "r"(a0), "r"(a1), "r"(a2), "r"(a3), "r"(b0), "r"(b1));
}
static __device__ __forceinline__ uint32_t bf16x2(float lo, float hi) {
    return (uint32_t)__bfloat16_as_ushort(__float2bfloat16_rn(lo))
         | ((uint32_t)__bfloat16_as_ushort(__float2bfloat16_rn(hi)) << 16);
}
static __device__ __forceinline__ uint32_t smem_u32(const void* p) {
    uint32_t a;
    asm("{ .reg .u64 t; cvta.to.shared.u64 t, %1; cvt.u32.u64 %0, t; }" : "=r"(a) : "l"(p));
    return a;
}
static __device__ __forceinline__ void cp16(uint32_t s, const void* g) {
    asm volatile("cp.async.cg.shared.global [%0], [%1], 16;" :: "r"(s), "l"(g));
}
static __device__ __forceinline__ void lds128(uint4& v, uint32_t addr) {
    asm volatile("ld.shared.v4.u32 {%0,%1,%2,%3}, [%4];"
                 : "=r"(v.x), "=r"(v.y), "=r"(v.z), "=r"(v.w) : "r"(addr));
}

// ---------------- fused prep kernel (unchanged, proven) ----------------
__global__ void __launch_bounds__(512) prep_kernel(const float* __restrict__ x,
                                                   const float* __restrict__ w,
                                                   int qBlocks) {
    __shared__ int8_t sm[16 * SM_STRIDE];
    int tid = threadIdx.x, warp = tid >> 5, lane = tid & 31;

    if ((int)blockIdx.x < qBlocks) {
        int mg = blockIdx.x;
        int t = mg * 16 + warp;
        const float4* xr = (const float4*)(x + (size_t)t * IN_F);
        float4 v[8];
        float m = 0.0f;
#pragma unroll
        for (int i = 0; i < 8; i++) {
            v[i] = xr[lane + 32 * i];
            m = fmaxf(m, fmaxf(fmaxf(fabsf(v[i].x), fabsf(v[i].y)),
                               fmaxf(fabsf(v[i].z), fabsf(v[i].w))));
        }
#pragma unroll
        for (int o = 16; o > 0; o >>= 1) m = fmaxf(m, __shfl_xor_sync(0xFFFFFFFFu, m, o));
        float scale = __fdiv_rn(fmaxf(m, 1e-8f), 127.0f);

#pragma unroll
        for (int i = 0; i < 8; i++) {
            float q0 = fminf(fmaxf(rintf(__fdiv_rn(v[i].x, scale)), -128.0f), 127.0f);
            float q1 = fminf(fmaxf(rintf(__fdiv_rn(v[i].y, scale)), -128.0f), 127.0f);
            float q2 = fminf(fmaxf(rintf(__fdiv_rn(v[i].z, scale)), -128.0f), 127.0f);
            float q3 = fminf(fmaxf(rintf(__fdiv_rn(v[i].w, scale)), -128.0f), 127.0f);
            uint2 pr = make_uint2(bf16x2(q0, q1), bf16x2(q2, q3));
            *(uint2*)(sm + warp * SM_STRIDE + 8 * lane + 256 * i) = pr;
        }
        if (lane == 0) g_xs[t] = scale;
        __syncthreads();

#pragma unroll
        for (int it = 0; it < 4; it++) {
            int u = tid + it * 512;
            int kb = u >> 5, l2 = u & 31;
            int g = l2 >> 2, t4 = l2 & 3;
            int bo = kb * 32 + t4 * 4;
            uint4 f;
            f.x = *(const uint32_t*)(sm + g * SM_STRIDE + bo);
            f.y = *(const uint32_t*)(sm + (g + 8) * SM_STRIDE + bo);
            f.z = *(const uint32_t*)(sm + g * SM_STRIDE + bo + 16);
            f.w = *(const uint32_t*)(sm + (g + 8) * SM_STRIDE + bo + 16);
            *(uint4*)((int8_t*)g_xa + ((((size_t)mg * 64 + kb) << 5) + l2) * 16) = f;
        }
    } else {
        int wb = blockIdx.x - qBlocks;
        int o = wb * 16 + warp;
        const float4* wr = (const float4*)(w + (size_t)o * IN_F);
        float am[8];
#pragma unroll
        for (int i = 0; i < 8; i++) {
            float4 v = wr[lane + 32 * i];
            uint2 pr;
            pr.x = (((v.x > 0.0f) ? 0x3F80u : 0xBF80u))
                 | (((v.y > 0.0f) ? 0x3F80u : 0xBF80u) << 16);
            pr.y = (((v.z > 0.0f) ? 0x3F80u : 0xBF80u))
                 | (((v.w > 0.0f) ? 0x3F80u : 0xBF80u) << 16);
            *(uint2*)(sm + warp * SM_STRIDE + 8 * lane + 256 * i) = pr;
            am[i] = fmaxf(fmaxf(fabsf(v.x), fabsf(v.y)), fmaxf(fabsf(v.z), fabsf(v.w)));
        }
#pragma unroll
        for (int i = 0; i < 8; i++)
#pragma unroll
            for (int off = 16; off > 0; off >>= 1)
                am[i] = fmaxf(am[i], __shfl_xor_sync(0xFFFFFFFFu, am[i], off));
        if (lane == 0) {
            float s = 0.0f;
#pragma unroll
            for (int i = 0; i < 8; i++)
                s += __half2float(__float2half_rn(fmaxf(am[i], 1e-8f)));
            g_ws[o] = s * 0.125f;
        }
        __syncthreads();

#pragma unroll
        for (int it = 0; it < 4; it++) {
            int u = tid + it * 512;
            int nh = u >> 10, kbp = (u >> 5) & 31, l2 = u & 31;
            int c = l2 >> 2, t4 = l2 & 3;
            int row = nh * 8 + c;
            int bo = kbp * 64 + t4 * 4;
            uint4 f;
            f.x = *(const uint32_t*)(sm + row * SM_STRIDE + bo);
            f.y = *(const uint32_t*)(sm + row * SM_STRIDE + bo + 16);
            f.z = *(const uint32_t*)(sm + row * SM_STRIDE + bo + 32);
            f.w = *(const uint32_t*)(sm + row * SM_STRIDE + bo + 48);
            int ng = wb * 2 + nh;
            *(uint4*)((int8_t*)g_wb + ((((size_t)ng * 32 + kbp) << 5) + l2) * 16) = f;
        }
    }
}

// ---------------- persistent GEMM: continuous chunk stream across tiles ----------------
__global__ void __launch_bounds__(512, 1)
onebit_gemm_kernel(const float* __restrict__ bias, float* __restrict__ out, int ntiles) {
    extern __shared__ char smem[];
    uint32_t SB = smem_u32(smem);

    int tid = threadIdx.x, warp = tid >> 5, lane = tid & 31;
    int wm = warp >> 2;
    int wn = warp & 3;
    int bid = blockIdx.x, grid = gridDim.x;

    const uint4* Ag = (const uint4*)g_xa;       // [(mg*64 + kb)*32 + lane]
    const uint4* Bg = (const uint4*)g_wb;       // [(ng*32 + kbp)*32 + lane]

    // stage global-seq s: ord = s/16 -> tile = bid + ord*grid, chunk = s%16
    auto stage_seq = [&](int s) {
        int ord = s >> 4;
        int t = bid + ord * grid;
        if (t < ntiles) {
            int chunk = s & 15;
            int mgS = (t >> 3) * 16;
            int ngS = (t & 7) * 16;
            uint32_t dst = SB + (uint32_t)(s % NSTAGE) * STAGE_BYTES;
#pragma unroll
            for (int it = 0; it < 4; it++) {
                int u = tid + it * 512;
                int mg = u >> 7, kbl = (u >> 5) & 3, l2 = u & 31;
                cp16(dst + (uint32_t)u * 16,
                     Ag + ((((size_t)(mgS + mg)) * 64 + chunk * KB_CH + kbl) << 5) + l2);
            }
#pragma unroll
            for (int it = 0; it < 2; it++) {
                int u = tid + it * 512;
                int ng = u >> 6, kbpl = (u >> 5) & 1, l2 = u & 31;
                cp16(dst + A_CH_BYTES + (uint32_t)u * 16,
                     Bg + ((((size_t)(ngS + ng)) * 32 + chunk * (KB_CH / 2) + kbpl) << 5) + l2);
            }
        }
        asm volatile("cp.async.commit_group;" ::: "memory");   // keep group count uniform
    };

    stage_seq(0);
    stage_seq(1);

    uint32_t aWOff = (uint32_t)(((wm * 4) * KB_CH) * 32 + lane) * 16;
    uint32_t bWOff = (uint32_t)A_CH_BYTES
                   + (uint32_t)(((wn * 4) * (KB_CH / 2)) * 32 + lane) * 16;
    int g = lane >> 2, t4 = lane & 3;

    int seq = 0;
#pragma unroll 1
    for (int t = bid; t < ntiles; t += grid) {
        int m0 = (t >> 3) * TILE_M;
        int n0 = (t & 7) * TILE_N;

        float acc[4][4][4];
#pragma unroll
        for (int i = 0; i < 4; i++)
#pragma unroll
            for (int j = 0; j < 4; j++)
#pragma unroll
                for (int q = 0; q < 4; q++) acc[i][j][q] = 0.0f;

#pragma unroll 1
        for (int c = 0; c < CH_TILE; c++, seq++) {
            asm volatile("cp.async.wait_group 1;" ::: "memory");
            __syncthreads();

            uint32_t buf = SB + (uint32_t)(seq % NSTAGE) * STAGE_BYTES;
            uint32_t aW = buf + aWOff;
            uint32_t bW = buf + bWOff;

#pragma unroll
            for (int kbpl = 0; kbpl < KB_CH / 2; kbpl++) {
                uint4 bf[4];
#pragma unroll
                for (int j = 0; j < 4; j++)
                    lds128(bf[j], bW + (uint32_t)((j * (KB_CH / 2) + kbpl) * 32) * 16);

                uint4 af[4];
#pragma unroll
                for (int i = 0; i < 4; i++)
                    lds128(af[i], aW + (uint32_t)((i * KB_CH + 2 * kbpl) * 32) * 16);
#pragma unroll
                for (int i = 0; i < 4; i++)
#pragma unroll
                    for (int j = 0; j < 4; j++)
                        mma_bf16(acc[i][j], af[i].x, af[i].y, af[i].z, af[i].w,
                                 bf[j].x, bf[j].y);

#pragma unroll
                for (int i = 0; i < 4; i++)
                    lds128(af[i], aW + (uint32_t)((i * KB_CH + 2 * kbpl + 1) * 32) * 16);
#pragma unroll
                for (int i = 0; i < 4; i++)
#pragma unroll
                    for (int j = 0; j < 4; j++)
                        mma_bf16(acc[i][j], af[i].x, af[i].y, af[i].z, af[i].w,
                                 bf[j].z, bf[j].w);
            }

            stage_seq(seq + 2);     // next tile's chunks flow in seamlessly
        }

        // ---- epilogue (regs + gmem only; next tile's loads already in flight) ----
#pragma unroll
        for (int i = 0; i < 4; i++) {
            int r0 = m0 + wm * 64 + i * 16 + g;
            float sx0 = g_xs[r0];
            float sx1 = g_xs[r0 + 8];
            float* o0 = out + (size_t)r0 * OUT_F + n0;
            float* o1 = o0 + (size_t)8 * OUT_F;
#pragma unroll
            for (int j = 0; j < 4; j++) {
                int cc = wn * 32 + j * 8 + t4 * 2;
                float w0 = g_ws[n0 + cc], w1 = g_ws[n0 + cc + 1];
                float b0 = bias[n0 + cc], b1 = bias[n0 + cc + 1];
                float2 v0, v1;
                v0.x = acc[i][j][0] * sx0 * w0 + b0;
                v0.y = acc[i][j][1] * sx0 * w1 + b1;
                v1.x = acc[i][j][2] * sx1 * w0 + b0;
                v1.y = acc[i][j][3] * sx1 * w1 + b1;
                *(float2*)(o0 + cc) = v0;
                *(float2*)(o1 + cc) = v1;
            }
        }
    }
}

// ---------------- launch ----------------
extern "C" void kernel_launch(void* const* d_in, const int* in_sizes, int n_in,
                              void* d_out, int out_size) {
    const float* x    = (const float*)d_in[0];
    const float* w    = (const float*)d_in[1];
    const float* bias = (const float*)d_in[2];
    float* out = (float*)d_out;
    int tokens = in_sizes[0] / IN_F;

    int qBlocks = tokens / 16;
    prep_kernel<<<qBlocks + OUT_F / 16, 512>>>(x, w, qBlocks);

    cudaFuncSetAttribute(onebit_gemm_kernel,
                         cudaFuncAttributeMaxDynamicSharedMemorySize, GEMM_SMEM);
    int ntiles = (tokens / TILE_M) * (OUT_F / TILE_N);
    int grid = ntiles < GRID_P ? ntiles : GRID_P;
    onebit_gemm_kernel<<<grid, 512, GEMM_SMEM>>>(bias, out, ntiles);
}

// round 15
// speedup vs baseline: 1.6938x; 1.0964x over previous
#include <cuda_runtime.h>
#include <cuda_fp16.h>
#include <cuda_bf16.h>
#include <cstdint>
#include <cstddef>

// ---------------- problem constants ----------------
#define IN_F   1024
#define OUT_F  1024
#define MAX_TOKENS 32768
#define TILE_M 128
#define TILE_N 128

#define SM_STRIDE 2064    // prep-kernel smem row pad

// GEMM pipeline: chunk = 4 kb (2 kbp), 3-stage, 2 CTAs/SM
#define KB_CH    4
#define NCHUNK   16                                  // 64 kb total
#define NSTAGE   3
#define A_CH_BYTES (8 * KB_CH * 32 * 16)             // 16384
#define B_CH_BYTES (16 * (KB_CH/2) * 32 * 16)        // 16384
#define STAGE_BYTES (A_CH_BYTES + B_CH_BYTES)        // 32768
#define GEMM_SMEM (NSTAGE * STAGE_BYTES)             // 98304 per CTA (x2 = 192KB/SM)

// ---------------- scratch: bf16 fragment-major operand layouts ----------------
__device__ __align__(16) __nv_bfloat16 g_xa[(size_t)MAX_TOKENS * IN_F];
__device__ float g_xs[MAX_TOKENS];
__device__ __align__(16) __nv_bfloat16 g_wb[(size_t)OUT_F * IN_F];
__device__ float g_ws[OUT_F];

// ---------------- helpers ----------------
static __device__ __forceinline__ void mma_bf16(float* c, uint32_t a0, uint32_t a1,
                                                uint32_t a2, uint32_t a3,
                                                uint32_t b0, uint32_t b1) {
    asm volatile(
        "mma.sync.aligned.m16n8k16.row.col.f32.bf16.bf16.f32 "
        "{%0,%1,%2,%3}, {%4,%5,%6,%7}, {%8,%9}, {%0,%1,%2,%3};"
        : "+f"(c[0]), "+f"(c[1]), "+f"(c[2]), "+f"(c[3])
        : "r"(a0), "r"(a1), "r"(a2), "r"(a3), "r"(b0), "r"(b1));
}
static __device__ __forceinline__ uint32_t bf16x2(float lo, float hi) {
    return (uint32_t)__bfloat16_as_ushort(__float2bfloat16_rn(lo))
         | ((uint32_t)__bfloat16_as_ushort(__float2bfloat16_rn(hi)) << 16);
}
static __device__ __forceinline__ uint32_t smem_u32(const void* p) {
    uint32_t a;
    asm("{ .reg .u64 t; cvta.to.shared.u64 t, %1; cvt.u32.u64 %0, t; }" : "=r"(a) : "l"(p));
    return a;
}
static __device__ __forceinline__ void cp16(uint32_t s, const void* g) {
    asm volatile("cp.async.cg.shared.global [%0], [%1], 16;" :: "r"(s), "l"(g));
}
static __device__ __forceinline__ void lds128(uint4& v, uint32_t addr) {
    asm volatile("ld.shared.v4.u32 {%0,%1,%2,%3}, [%4];"
                 : "=r"(v.x), "=r"(v.y), "=r"(v.z), "=r"(v.w) : "r"(addr));
}

// ---------------- fused prep kernel (unchanged, proven) ----------------
__global__ void __launch_bounds__(512) prep_kernel(const float* __restrict__ x,
                                                   const float* __restrict__ w,
                                                   int qBlocks) {
    __shared__ int8_t sm[16 * SM_STRIDE];
    int tid = threadIdx.x, warp = tid >> 5, lane = tid & 31;

    if ((int)blockIdx.x < qBlocks) {
        int mg = blockIdx.x;
        int t = mg * 16 + warp;
        const float4* xr = (const float4*)(x + (size_t)t * IN_F);
        float4 v[8];
        float m = 0.0f;
#pragma unroll
        for (int i = 0; i < 8; i++) {
            v[i] = xr[lane + 32 * i];
            m = fmaxf(m, fmaxf(fmaxf(fabsf(v[i].x), fabsf(v[i].y)),
                               fmaxf(fabsf(v[i].z), fabsf(v[i].w))));
        }
#pragma unroll
        for (int o = 16; o > 0; o >>= 1) m = fmaxf(m, __shfl_xor_sync(0xFFFFFFFFu, m, o));
        float scale = __fdiv_rn(fmaxf(m, 1e-8f), 127.0f);

#pragma unroll
        for (int i = 0; i < 8; i++) {
            float q0 = fminf(fmaxf(rintf(__fdiv_rn(v[i].x, scale)), -128.0f), 127.0f);
            float q1 = fminf(fmaxf(rintf(__fdiv_rn(v[i].y, scale)), -128.0f), 127.0f);
            float q2 = fminf(fmaxf(rintf(__fdiv_rn(v[i].z, scale)), -128.0f), 127.0f);
            float q3 = fminf(fmaxf(rintf(__fdiv_rn(v[i].w, scale)), -128.0f), 127.0f);
            uint2 pr = make_uint2(bf16x2(q0, q1), bf16x2(q2, q3));
            *(uint2*)(sm + warp * SM_STRIDE + 8 * lane + 256 * i) = pr;
        }
        if (lane == 0) g_xs[t] = scale;
        __syncthreads();

#pragma unroll
        for (int it = 0; it < 4; it++) {
            int u = tid + it * 512;
            int kb = u >> 5, l2 = u & 31;
            int g = l2 >> 2, t4 = l2 & 3;
            int bo = kb * 32 + t4 * 4;
            uint4 f;
            f.x = *(const uint32_t*)(sm + g * SM_STRIDE + bo);
            f.y = *(const uint32_t*)(sm + (g + 8) * SM_STRIDE + bo);
            f.z = *(const uint32_t*)(sm + g * SM_STRIDE + bo + 16);
            f.w = *(const uint32_t*)(sm + (g + 8) * SM_STRIDE + bo + 16);
            *(uint4*)((int8_t*)g_xa + ((((size_t)mg * 64 + kb) << 5) + l2) * 16) = f;
        }
    } else {
        int wb = blockIdx.x - qBlocks;
        int o = wb * 16 + warp;
        const float4* wr = (const float4*)(w + (size_t)o * IN_F);
        float am[8];
#pragma unroll
        for (int i = 0; i < 8; i++) {
            float4 v = wr[lane + 32 * i];
            uint2 pr;
            pr.x = (((v.x > 0.0f) ? 0x3F80u : 0xBF80u))
                 | (((v.y > 0.0f) ? 0x3F80u : 0xBF80u) << 16);
            pr.y = (((v.z > 0.0f) ? 0x3F80u : 0xBF80u))
                 | (((v.w > 0.0f) ? 0x3F80u : 0xBF80u) << 16);
            *(uint2*)(sm + warp * SM_STRIDE + 8 * lane + 256 * i) = pr;
            am[i] = fmaxf(fmaxf(fabsf(v.x), fabsf(v.y)), fmaxf(fabsf(v.z), fabsf(v.w)));
        }
#pragma unroll
        for (int i = 0; i < 8; i++)
#pragma unroll
            for (int off = 16; off > 0; off >>= 1)
                am[i] = fmaxf(am[i], __shfl_xor_sync(0xFFFFFFFFu, am[i], off));
        if (lane == 0) {
            float s = 0.0f;
#pragma unroll
            for (int i = 0; i < 8; i++)
                s += __half2float(__float2half_rn(fmaxf(am[i], 1e-8f)));
            g_ws[o] = s * 0.125f;
        }
        __syncthreads();

#pragma unroll
        for (int it = 0; it < 4; it++) {
            int u = tid + it * 512;
            int nh = u >> 10, kbp = (u >> 5) & 31, l2 = u & 31;
            int c = l2 >> 2, t4 = l2 & 3;
            int row = nh * 8 + c;
            int bo = kbp * 64 + t4 * 4;
            uint4 f;
            f.x = *(const uint32_t*)(sm + row * SM_STRIDE + bo);
            f.y = *(const uint32_t*)(sm + row * SM_STRIDE + bo + 16);
            f.z = *(const uint32_t*)(sm + row * SM_STRIDE + bo + 32);
            f.w = *(const uint32_t*)(sm + row * SM_STRIDE + bo + 48);
            int ng = wb * 2 + nh;
            *(uint4*)((int8_t*)g_wb + ((((size_t)ng * 32 + kbp) << 5) + l2) * 16) = f;
        }
    }
}

// ---------------- GEMM: 128x128 tile, 256 threads, 2 CTAs/SM ----------------
__global__ void __launch_bounds__(256, 2)
onebit_gemm_kernel(const float* __restrict__ bias, float* __restrict__ out) {
    extern __shared__ char smem[];
    uint32_t SB = smem_u32(smem);

    int tid = threadIdx.x, warp = tid >> 5, lane = tid & 31;
    int wm = warp >> 2;            // 0..1 -> 64-row slab of 128
    int wn = warp & 3;             // 0..3 -> 32-col slab of 128
    int n_blk = blockIdx.x & 7;
    int m_blk = blockIdx.x >> 3;
    int m0 = m_blk * TILE_M, n0 = n_blk * TILE_N;

    int mgB0 = m_blk * 8;          // 8 m-groups per tile
    int ngB0 = n_blk * 16;         // 16 n-groups per tile

    const uint4* Ag = (const uint4*)g_xa;       // [(mg*64 + kb)*32 + lane]
    const uint4* Bg = (const uint4*)g_wb;       // [(ng*32 + kbp)*32 + lane]

    // stage chunk c (4 kb of A, 2 kbp of B) into buffer (c % 3): 2048 cp16 / 256 thr
    auto stage_chunk = [&](int c) {
        uint32_t dst = SB + (uint32_t)(c % NSTAGE) * STAGE_BYTES;
        // A: 1024 uint4; smem order [mg 0..7][kbl 0..3][lane]
#pragma unroll
        for (int it = 0; it < 4; it++) {
            int u = tid + it * 256;
            int mg = u >> 7, kbl = (u >> 5) & 3, l2 = u & 31;
            cp16(dst + (uint32_t)u * 16,
                 Ag + ((((size_t)(mgB0 + mg)) * 64 + c * KB_CH + kbl) << 5) + l2);
        }
        // B: 1024 uint4; smem order [ng 0..15][kbpl 0..1][lane]
#pragma unroll
        for (int it = 0; it < 4; it++) {
            int u = tid + it * 256;
            int ng = u >> 6, kbpl = (u >> 5) & 1, l2 = u & 31;
            cp16(dst + A_CH_BYTES + (uint32_t)u * 16,
                 Bg + ((((size_t)(ngB0 + ng)) * 32 + c * (KB_CH / 2) + kbpl) << 5) + l2);
        }
        asm volatile("cp.async.commit_group;" ::: "memory");
    };

    stage_chunk(0);
    stage_chunk(1);

    float acc[4][4][4];
#pragma unroll
    for (int i = 0; i < 4; i++)
#pragma unroll
        for (int j = 0; j < 4; j++)
#pragma unroll
            for (int q = 0; q < 4; q++) acc[i][j][q] = 0.0f;

    uint32_t aWOff = (uint32_t)(((wm * 4) * KB_CH) * 32 + lane) * 16;
    uint32_t bWOff = (uint32_t)A_CH_BYTES
                   + (uint32_t)(((wn * 4) * (KB_CH / 2)) * 32 + lane) * 16;

#pragma unroll 1
    for (int c = 0; c < NCHUNK; c++) {
        // Invariant: newest committed group at this point is chunk c+1's
        // (empty groups keep the count uniform past the last real stage),
        // so wait_group 1 guarantees chunk c's data has fully landed.
        asm volatile("cp.async.wait_group 1;" ::: "memory");
        __syncthreads();

        uint32_t buf = SB + (uint32_t)(c % NSTAGE) * STAGE_BYTES;
        uint32_t aW = buf + aWOff;
        uint32_t bW = buf + bWOff;

#pragma unroll
        for (int kbpl = 0; kbpl < KB_CH / 2; kbpl++) {
            uint4 bf[4];
#pragma unroll
            for (int j = 0; j < 4; j++)
                lds128(bf[j], bW + (uint32_t)((j * (KB_CH / 2) + kbpl) * 32) * 16);

            uint4 af[4];
#pragma unroll
            for (int i = 0; i < 4; i++)
                lds128(af[i], aW + (uint32_t)((i * KB_CH + 2 * kbpl) * 32) * 16);
#pragma unroll
            for (int i = 0; i < 4; i++)
#pragma unroll
                for (int j = 0; j < 4; j++)
                    mma_bf16(acc[i][j], af[i].x, af[i].y, af[i].z, af[i].w,
                             bf[j].x, bf[j].y);

#pragma unroll
            for (int i = 0; i < 4; i++)
                lds128(af[i], aW + (uint32_t)((i * KB_CH + 2 * kbpl + 1) * 32) * 16);
#pragma unroll
            for (int i = 0; i < 4; i++)
#pragma unroll
                for (int j = 0; j < 4; j++)
                    mma_bf16(acc[i][j], af[i].x, af[i].y, af[i].z, af[i].w,
                             bf[j].z, bf[j].w);
        }

        if (c + 2 < NCHUNK) {
            stage_chunk(c + 2);
        } else {
            // empty commit: keeps group accounting uniform so the final
            // chunks' wait_group 1 retires THEIR data groups (race fix)
            asm volatile("cp.async.commit_group;" ::: "memory");
        }
    }

    // ---------------- fused epilogue ----------------
    int g = lane >> 2, t4 = lane & 3;
#pragma unroll
    for (int i = 0; i < 4; i++) {
        int r0 = m0 + wm * 64 + i * 16 + g;
        float sx0 = g_xs[r0];
        float sx1 = g_xs[r0 + 8];
        float* o0 = out + (size_t)r0 * OUT_F + n0;
        float* o1 = o0 + (size_t)8 * OUT_F;
#pragma unroll
        for (int j = 0; j < 4; j++) {
            int cc = wn * 32 + j * 8 + t4 * 2;
            float w0 = g_ws[n0 + cc], w1 = g_ws[n0 + cc + 1];
            float b0 = bias[n0 + cc], b1 = bias[n0 + cc + 1];
            float2 v0, v1;
            v0.x = acc[i][j][0] * sx0 * w0 + b0;
            v0.y = acc[i][j][1] * sx0 * w1 + b1;
            v1.x = acc[i][j][2] * sx1 * w0 + b0;
            v1.y = acc[i][j][3] * sx1 * w1 + b1;
            *(float2*)(o0 + cc) = v0;
            *(float2*)(o1 + cc) = v1;
        }
    }
}

// ---------------- launch ----------------
extern "C" void kernel_launch(void* const* d_in, const int* in_sizes, int n_in,
                              void* d_out, int out_size) {
    const float* x    = (const float*)d_in[0];
    const float* w    = (const float*)d_in[1];
    const float* bias = (const float*)d_in[2];
    float* out = (float*)d_out;
    int tokens = in_sizes[0] / IN_F;

    int qBlocks = tokens / 16;
    prep_kernel<<<qBlocks + OUT_F / 16, 512>>>(x, w, qBlocks);

    cudaFuncSetAttribute(onebit_gemm_kernel,
                         cudaFuncAttributeMaxDynamicSharedMemorySize, GEMM_SMEM);
    int mtiles = tokens / TILE_M;
    onebit_gemm_kernel<<<mtiles * (OUT_F / TILE_N), 256, GEMM_SMEM>>>(bias, out);
}